// round 14
// baseline (speedup 1.0000x reference)
#include <cuda_runtime.h>
#include <cuda_fp16.h>
#include <cstdint>
#include <stdint.h>
#include <mma.h>

using namespace nvcuda;

#define D_MODEL  2048
#define D_STATE  128
#define D_CONV   4
#define D_SSM    4096
#define NHEADS   64
#define HEADDIM  64
#define CONV_DIM (D_SSM + 2*D_STATE)                 // 4352
#define D_IN_PROJ (2*D_SSM + 2*D_STATE + NHEADS)     // 8512
#define BATCH    256
#define N_GEMM   8448                                // in_proj cols via GEMM (dt exact)

#define OUT_CONV (BATCH*D_MODEL)                     // 524288
#define OUT_SSM  (OUT_CONV + BATCH*CONV_DIM*D_CONV)  // 4980736

// ---------------- scratch ----------------
__device__ float  g_zxbcdt[(size_t)BATCH * D_IN_PROJ];
__device__ float  g_x[BATCH * D_SSM];
__device__ float  g_B[BATCH * D_STATE];
__device__ float  g_C[BATCH * D_STATE];
__device__ float  g_dt[BATCH * NHEADS];
__device__ float  g_dA[BATCH * NHEADS];
__device__ __half g_yg_h[BATCH * D_SSM];
__device__ __half g_hid_h[BATCH * D_MODEL];

// ---------------- cp.async helpers ----------------
__device__ __forceinline__ void cp_async16(void* smem, const void* g) {
    unsigned int s = (unsigned int)__cvta_generic_to_shared(smem);
    asm volatile("cp.async.cg.shared.global [%0], [%1], 16;\n" :: "r"(s), "l"(g));
}
__device__ __forceinline__ void cp_commit() {
    asm volatile("cp.async.commit_group;\n");
}
template<int N>
__device__ __forceinline__ void cp_wait() {
    asm volatile("cp.async.wait_group %0;\n" :: "n"(N));
}

// ---------------- fp32 -> fp16 convert (8 elems / thread) — for hid only ----------------
__global__ void f2h_kernel(const float* __restrict__ in, __half* __restrict__ out, int n8)
{
    int i = blockIdx.x * blockDim.x + threadIdx.x;
    if (i >= n8) return;
    const float4* p = reinterpret_cast<const float4*>(in) + (size_t)i * 2;
    float4 a = p[0], b = p[1];
    __half2 h[4];
    h[0] = __floats2half2_rn(a.x, a.y);
    h[1] = __floats2half2_rn(a.z, a.w);
    h[2] = __floats2half2_rn(b.x, b.y);
    h[3] = __floats2half2_rn(b.z, b.w);
    reinterpret_cast<uint2*>(out)[ (size_t)i * 2 + 0 ] = *reinterpret_cast<uint2*>(&h[0]);
    reinterpret_cast<uint2*>(out)[ (size_t)i * 2 + 1 ] = *reinterpret_cast<uint2*>(&h[2]);
}

// ============ fused-convert GEMM: C[M,N] = A16[M,K] * (f16(W32))[N,K]^T ============
// A arrives fp16; W arrives fp32 and is converted smem->smem per K-tile.
// DEPTH-3 cp.async ring for A16/W32; ping-pong fp16 W buffer for the mma phase.
#define GDEPTH 3

template<int BM, int BN, int BK, int WM, int WN>
__global__ void gemm_f16wc(const __half* __restrict__ A, const float* __restrict__ W,
                           float* __restrict__ C, int M, int N, int K)
{
    constexpr int WARPS_M = BM / WM;
    constexpr int WARPS_N = BN / WN;
    constexpr int THREADS = WARPS_M * WARPS_N * 32;
    constexpr int FM = WM / 16, FN = WN / 16;
    constexpr int LDh = BK + 8;                 // halves
    constexpr int AKV = BK / 8;                 // 16B chunks per A row
    constexpr int WKV = BK / 4;                 // float4 chunks per W row
    constexpr int APT = BM * AKV / THREADS;
    constexpr int WPT = BN * WKV / THREADS;     // also convert chunks per thread

    extern __shared__ char smraw[];
    __half* A16 = reinterpret_cast<__half*>(smraw);                       // [3][BM][LDh]
    __half* W16 = A16 + GDEPTH * BM * LDh;                                // [2][BN][LDh]
    float*  W32 = reinterpret_cast<float*>(W16 + 2 * BN * LDh);           // [3][BN][BK]

    const int tid  = threadIdx.x;
    const int warp = tid >> 5;
    const int wm = warp / WARPS_N, wn = warp % WARPS_N;
    const int row0 = blockIdx.y * BM;
    const int col0 = blockIdx.x * BN;

    wmma::fragment<wmma::accumulator, 16, 16, 16, float> acc[FM][FN];
    #pragma unroll
    for (int i = 0; i < FM; i++)
        #pragma unroll
        for (int j = 0; j < FN; j++)
            wmma::fill_fragment(acc[i][j], 0.0f);

    const __half* Abase = A + (size_t)row0 * K;
    const float*  Wbase = W + (size_t)col0 * K;

    auto load_tile = [&](int t) {
        const int buf = t % GDEPTH;
        const __half* Ag = Abase + t * BK;
        const float*  Wg = Wbase + t * BK;
        __half* Ab = A16 + buf * BM * LDh;
        float*  Wb = W32 + buf * BN * BK;
        #pragma unroll
        for (int u = 0; u < APT; u++) {
            int v = tid + u * THREADS;
            int r = v / AKV, kq = v % AKV;
            cp_async16(Ab + r * LDh + kq * 8, Ag + (size_t)r * K + kq * 8);
        }
        #pragma unroll
        for (int u = 0; u < WPT; u++) {
            int v = tid + u * THREADS;
            int r = v / WKV, kq = v % WKV;
            cp_async16(Wb + r * BK + kq * 4, Wg + (size_t)r * K + kq * 4);
        }
        cp_commit();
    };

    const int T = K / BK;
    load_tile(0);
    load_tile(1);

    for (int t = 0; t < T; t++) {
        if (t + 1 < T) cp_wait<1>();
        else           cp_wait<0>();
        __syncthreads();

        if (t + 2 < T) load_tile(t + 2);

        // convert fp32 W tile -> fp16 ping-pong buffer
        {
            const float* w32 = W32 + (t % GDEPTH) * BN * BK;
            __half* w16 = W16 + (t & 1) * BN * LDh;
            #pragma unroll
            for (int u = 0; u < WPT; u++) {
                int v = tid + u * THREADS;
                int r = v / WKV, q = v % WKV;
                float4 f = reinterpret_cast<const float4*>(w32 + r * BK)[q];
                __half2 h0 = __floats2half2_rn(f.x, f.y);
                __half2 h1 = __floats2half2_rn(f.z, f.w);
                uint2 pk;
                pk.x = *reinterpret_cast<unsigned*>(&h0);
                pk.y = *reinterpret_cast<unsigned*>(&h1);
                *reinterpret_cast<uint2*>(w16 + r * LDh + q * 4) = pk;
            }
        }
        __syncthreads();

        const __half* Ab = A16 + (t % GDEPTH) * BM * LDh;
        const __half* Bb = W16 + (t & 1) * BN * LDh;
        #pragma unroll
        for (int kk = 0; kk < BK; kk += 16) {
            wmma::fragment<wmma::matrix_a, 16, 16, 16, half, wmma::row_major> af[FM];
            wmma::fragment<wmma::matrix_b, 16, 16, 16, half, wmma::col_major> bf[FN];
            #pragma unroll
            for (int i = 0; i < FM; i++)
                wmma::load_matrix_sync(af[i], Ab + (wm * WM + 16 * i) * LDh + kk, LDh);
            #pragma unroll
            for (int j = 0; j < FN; j++)
                wmma::load_matrix_sync(bf[j], Bb + (wn * WN + 16 * j) * LDh + kk, LDh);
            #pragma unroll
            for (int i = 0; i < FM; i++)
                #pragma unroll
                for (int j = 0; j < FN; j++)
                    wmma::mma_sync(acc[i][j], af[i], bf[j], acc[i][j]);
        }
        // NOTE: no trailing sync needed; top-of-loop sync orders reuse.
    }

    #pragma unroll
    for (int i = 0; i < FM; i++)
        #pragma unroll
        for (int j = 0; j < FN; j++)
            wmma::store_matrix_sync(C + (size_t)(row0 + wm * WM + 16 * i) * N
                                      + (col0 + wn * WN + 16 * j),
                                    acc[i][j], N, wmma::mem_row_major);
}

// in_proj:  BM=128,BN=128,BK=32, warps 2x2 of 64x64, 128 thr, grid (66,2)
//   smem = 3*128*40*2 + 2*128*40*2 + 3*128*32*4 = 100352 B
// out_proj: BM=64,BN=64,BK=64, warps 2x2 of 32x32, 128 thr, grid (32,4)
//   smem = 3*64*72*2 + 2*64*72*2 + 3*64*64*4 = 95232 B
#define IN_SMEM  (GDEPTH*128*(32+8)*2 + 2*128*(32+8)*2 + GDEPTH*128*32*4)
#define OUT_SMEM (GDEPTH*64*(64+8)*2 + 2*64*(64+8)*2 + GDEPTH*64*64*4)

// ---------------- exact fp32 dt path ----------------
__global__ void dt_kernel(const float* __restrict__ hid, const float* __restrict__ Wp,
                          const float* __restrict__ dt_bias, const float* __restrict__ A_log)
{
    int w = (blockIdx.x * blockDim.x + threadIdx.x) >> 5;
    int lane = threadIdx.x & 31;
    if (w >= BATCH * NHEADS) return;
    int b = w >> 6, h = w & 63;
    const float* hr = hid + (size_t)b * D_MODEL;
    const float* wr = Wp + (size_t)(D_SSM + CONV_DIM + h) * D_MODEL;
    float s = 0.0f;
    #pragma unroll 4
    for (int k = lane; k < D_MODEL; k += 32) s = fmaf(hr[k], wr[k], s);
    #pragma unroll
    for (int o = 16; o; o >>= 1) s += __shfl_xor_sync(0xffffffffu, s, o);
    if (lane == 0) {
        float v = s + dt_bias[h];
        float dt = (v > 20.0f) ? v : log1pf(expf(v));
        g_dt[w] = dt;
        g_dA[w] = expf(-dt * expf(A_log[h]));
    }
}

// ---------------- conv ----------------
__global__ void conv_kernel(const float* __restrict__ conv_state,
                            const float* __restrict__ conv_w,
                            const float* __restrict__ conv_b,
                            float* __restrict__ out_conv)
{
    int i = blockIdx.x * blockDim.x + threadIdx.x;
    if (i >= BATCH * CONV_DIM) return;
    int b = i / CONV_DIM;
    int c = i - b * CONV_DIM;

    float4 s = reinterpret_cast<const float4*>(conv_state)[i];
    float xin = g_zxbcdt[(size_t)b * D_IN_PROJ + D_SSM + c];
    float4 ns = make_float4(s.y, s.z, s.w, xin);
    reinterpret_cast<float4*>(out_conv)[i] = ns;

    float4 w = reinterpret_cast<const float4*>(conv_w)[c];
    float v = ns.x*w.x + ns.y*w.y + ns.z*w.z + ns.w*w.w + conv_b[c];
    v = v / (1.0f + expf(-v));

    if (c < D_SSM) {
        g_x[b * D_SSM + c] = v;
    } else if (c < D_SSM + D_STATE) {
        g_B[b * D_STATE + (c - D_SSM)] = v;
    } else {
        g_C[b * D_STATE + (c - D_SSM - D_STATE)] = v;
    }
}

// ---------------- ssm state update + y + gating (writes yg as fp16) ----------------
__global__ void __launch_bounds__(256)
ssm_kernel(const float* __restrict__ ssm_in,
           const float* __restrict__ Dv,
           float* __restrict__ out_ssm)
{
    int bi = blockIdx.x;              // b*64 + h
    int b = bi >> 6, h = bi & 63;
    int warp = threadIdx.x >> 5, lane = threadIdx.x & 31;

    float dA = g_dA[bi];
    float dt = g_dt[bi];
    float Dh = Dv[h];
    float4 Bv = reinterpret_cast<const float4*>(g_B + b * D_STATE)[lane];
    float4 Cv = reinterpret_cast<const float4*>(g_C + b * D_STATE)[lane];
    const float* xrow = g_x + (size_t)b * D_SSM + h * HEADDIM;
    size_t base = (size_t)bi * (HEADDIM * D_STATE);
    const float4* src = reinterpret_cast<const float4*>(ssm_in + base);
    float4* dst = reinterpret_cast<float4*>(out_ssm + base);

    #pragma unroll
    for (int half_i = 0; half_i < 2; half_i++) {
        float4 s[4];
        float xp[4];
        #pragma unroll
        for (int r = 0; r < 4; r++) {
            int p = warp * 8 + half_i * 4 + r;
            s[r] = __ldcs(&src[p * 32 + lane]);
            xp[r] = __ldg(&xrow[p]);
        }

        float part[4];
        #pragma unroll
        for (int r = 0; r < 4; r++) {
            int p = warp * 8 + half_i * 4 + r;
            float coef = dt * xp[r];
            float4 ns;
            ns.x = fmaf(s[r].x, dA, coef * Bv.x);
            ns.y = fmaf(s[r].y, dA, coef * Bv.y);
            ns.z = fmaf(s[r].z, dA, coef * Bv.z);
            ns.w = fmaf(s[r].w, dA, coef * Bv.w);
            __stcs(&dst[p * 32 + lane], ns);
            part[r] = ns.x*Cv.x + ns.y*Cv.y + ns.z*Cv.z + ns.w*Cv.w;
        }

        #pragma unroll
        for (int r = 0; r < 4; r++) {
            #pragma unroll
            for (int o = 16; o; o >>= 1) part[r] += __shfl_xor_sync(0xffffffffu, part[r], o);
            if (lane == 0) {
                int p = warp * 8 + half_i * 4 + r;
                float y = part[r] + Dh * xp[r];
                float z = g_zxbcdt[(size_t)b * D_IN_PROJ + h * HEADDIM + p];
                g_yg_h[b * D_SSM + h * HEADDIM + p] = __float2half(y * (z / (1.0f + expf(-z))));
            }
        }
    }
}

// ---------------- launch ----------------
extern "C" void kernel_launch(void* const* d_in, const int* in_sizes, int n_in,
                              void* d_out, int out_size)
{
    const float* hid        = (const float*)d_in[0];
    const float* conv_state = (const float*)d_in[1];
    const float* ssm_state  = (const float*)d_in[2];
    const float* in_proj_w  = (const float*)d_in[3];
    const float* conv_w     = (const float*)d_in[4];
    const float* conv_b     = (const float*)d_in[5];
    const float* dt_bias    = (const float*)d_in[6];
    const float* A_log      = (const float*)d_in[7];
    const float* Dv         = (const float*)d_in[8];
    const float* out_proj_w = (const float*)d_in[9];
    float* out = (float*)d_out;

    void* zx_p;  cudaGetSymbolAddress(&zx_p, g_zxbcdt);
    void* yg_p;  cudaGetSymbolAddress(&yg_p, g_yg_h);
    void* hid_p; cudaGetSymbolAddress(&hid_p, g_hid_h);

    cudaFuncSetAttribute(gemm_f16wc<128,128,32,64,64>,
                         cudaFuncAttributeMaxDynamicSharedMemorySize, IN_SMEM);
    cudaFuncSetAttribute(gemm_f16wc<64,64,64,32,32>,
                         cudaFuncAttributeMaxDynamicSharedMemorySize, OUT_SMEM);

    // exact dt/dA path
    dt_kernel<<<(BATCH * NHEADS * 32) / 256, 256>>>(hid, in_proj_w, dt_bias, A_log);

    // hid fp32 -> fp16 (tiny)
    f2h_kernel<<<(BATCH * D_MODEL / 8 + 255) / 256, 256>>>(hid, (__half*)hid_p,
                                                           BATCH * D_MODEL / 8);

    // in_proj: [256, 8448] = hid @ in_proj_w^T (W converted in-kernel)
    gemm_f16wc<128,128,32,64,64><<<dim3(N_GEMM/128, BATCH/128), 128, IN_SMEM>>>(
        (const __half*)hid_p, in_proj_w, (float*)zx_p, BATCH, D_IN_PROJ, D_MODEL);

    // conv roll + depthwise conv + silu -> new conv_state + x/B/C
    conv_kernel<<<(BATCH * CONV_DIM) / 256, 256>>>(conv_state, conv_w, conv_b, out + OUT_CONV);

    // ssm update (1.07 GB pass) + fused y/gating -> yg fp16
    ssm_kernel<<<BATCH * NHEADS, 256>>>(ssm_state, Dv, out + OUT_SSM);

    // out_proj: [256, 2048] = yg @ out_proj_w^T (W converted in-kernel), 128 CTAs
    gemm_f16wc<64,64,64,32,32><<<dim3(D_MODEL/64, BATCH/64), 128, OUT_SMEM>>>(
        (const __half*)yg_p, out_proj_w, out, BATCH, D_MODEL, D_SSM);
}

// round 16
// speedup vs baseline: 1.0029x; 1.0029x over previous
#include <cuda_runtime.h>
#include <cuda_fp16.h>
#include <cstdint>
#include <stdint.h>
#include <mma.h>

using namespace nvcuda;

#define D_MODEL  2048
#define D_STATE  128
#define D_CONV   4
#define D_SSM    4096
#define NHEADS   64
#define HEADDIM  64
#define CONV_DIM (D_SSM + 2*D_STATE)                 // 4352
#define D_IN_PROJ (2*D_SSM + 2*D_STATE + NHEADS)     // 8512
#define BATCH    256
#define N_GEMM   8448                                // in_proj cols via GEMM (dt exact)

#define OUT_CONV (BATCH*D_MODEL)                     // 524288
#define OUT_SSM  (OUT_CONV + BATCH*CONV_DIM*D_CONV)  // 4980736

// ---------------- scratch ----------------
__device__ float  g_zxbcdt[(size_t)BATCH * D_IN_PROJ];
__device__ float  g_x[BATCH * D_SSM];
__device__ float  g_B[BATCH * D_STATE];
__device__ float  g_C[BATCH * D_STATE];
__device__ float  g_dt[BATCH * NHEADS];
__device__ float  g_dA[BATCH * NHEADS];
__device__ __half g_yg_h[BATCH * D_SSM];
__device__ __half g_hid_h[BATCH * D_MODEL];
__device__ __half g_inw_h[(size_t)N_GEMM * D_MODEL];     // 34.6 MB
__device__ __half g_outw_h[(size_t)D_MODEL * D_SSM];     // 16.8 MB

// ---------------- cp.async helpers ----------------
__device__ __forceinline__ void cp_async16(void* smem, const void* g) {
    unsigned int s = (unsigned int)__cvta_generic_to_shared(smem);
    asm volatile("cp.async.cg.shared.global [%0], [%1], 16;\n" :: "r"(s), "l"(g));
}
__device__ __forceinline__ void cp_commit() {
    asm volatile("cp.async.commit_group;\n");
}
template<int N>
__device__ __forceinline__ void cp_wait() {
    asm volatile("cp.async.wait_group %0;\n" :: "n"(N));
}

// ---------------- fp32 -> fp16 convert (16 elems / thread, MLP 4, streaming) ----------------
__global__ void f2h_kernel(const float* __restrict__ in, __half* __restrict__ out, int n16)
{
    int i = blockIdx.x * blockDim.x + threadIdx.x;
    if (i >= n16) return;
    const float4* p = reinterpret_cast<const float4*>(in) + (size_t)i * 4;
    float4 a = __ldcs(&p[0]);
    float4 b = __ldcs(&p[1]);
    float4 c = __ldcs(&p[2]);
    float4 d = __ldcs(&p[3]);
    __half2 h[8];
    h[0] = __floats2half2_rn(a.x, a.y);  h[1] = __floats2half2_rn(a.z, a.w);
    h[2] = __floats2half2_rn(b.x, b.y);  h[3] = __floats2half2_rn(b.z, b.w);
    h[4] = __floats2half2_rn(c.x, c.y);  h[5] = __floats2half2_rn(c.z, c.w);
    h[6] = __floats2half2_rn(d.x, d.y);  h[7] = __floats2half2_rn(d.z, d.w);
    float4* o = reinterpret_cast<float4*>(out) + (size_t)i * 2;
    __stcs(&o[0], *reinterpret_cast<float4*>(&h[0]));
    __stcs(&o[1], *reinterpret_cast<float4*>(&h[4]));
}

// ---------------- tiled double-buffered fp16 GEMM: C[M,N] = A[M,K] * W[N,K]^T ----------------
template<int BM, int BN, int BK, int WM, int WN>
__global__ void gemm_f16(const __half* __restrict__ A, const __half* __restrict__ W,
                         float* __restrict__ C, int M, int N, int K)
{
    constexpr int WARPS_M = BM / WM;
    constexpr int WARPS_N = BN / WN;
    constexpr int THREADS = WARPS_M * WARPS_N * 32;
    constexpr int FM = WM / 16, FN = WN / 16;
    constexpr int LD = BK + 8;                 // halves; 16B-aligned rows, conflict pad
    constexpr int KV = BK / 8;                 // 16B chunks per row
    constexpr int AV = BM * KV, BV = BN * KV;
    constexpr int APT = AV / THREADS, BPT = BV / THREADS;

    extern __shared__ __half sm[];
    __half* As = sm;                           // [2][BM][LD]
    __half* Bs = sm + 2 * BM * LD;             // [2][BN][LD]

    const int tid  = threadIdx.x;
    const int warp = tid >> 5;
    const int wm = warp / WARPS_N, wn = warp % WARPS_N;
    const int row0 = blockIdx.y * BM;
    const int col0 = blockIdx.x * BN;

    wmma::fragment<wmma::accumulator, 16, 16, 16, float> acc[FM][FN];
    #pragma unroll
    for (int i = 0; i < FM; i++)
        #pragma unroll
        for (int j = 0; j < FN; j++)
            wmma::fill_fragment(acc[i][j], 0.0f);

    const __half* Abase = A + (size_t)row0 * K;
    const __half* Wbase = W + (size_t)col0 * K;

    auto load_tile = [&](int t, int buf) {
        const __half* Ag = Abase + t * BK;
        const __half* Wg = Wbase + t * BK;
        __half* Ab = As + buf * BM * LD;
        __half* Bb = Bs + buf * BN * LD;
        #pragma unroll
        for (int u = 0; u < APT; u++) {
            int v = tid + u * THREADS;
            int r = v / KV, kq = v % KV;
            cp_async16(Ab + r * LD + kq * 8, Ag + (size_t)r * K + kq * 8);
        }
        #pragma unroll
        for (int u = 0; u < BPT; u++) {
            int v = tid + u * THREADS;
            int r = v / KV, kq = v % KV;
            cp_async16(Bb + r * LD + kq * 8, Wg + (size_t)r * K + kq * 8);
        }
        cp_commit();
    };

    const int T = K / BK;
    load_tile(0, 0);

    for (int t = 0; t < T; t++) {
        int buf = t & 1;
        if (t + 1 < T) { load_tile(t + 1, buf ^ 1); cp_wait<1>(); }
        else           { cp_wait<0>(); }
        __syncthreads();

        const __half* Ab = As + buf * BM * LD;
        const __half* Bb = Bs + buf * BN * LD;
        #pragma unroll
        for (int kk = 0; kk < BK; kk += 16) {
            wmma::fragment<wmma::matrix_a, 16, 16, 16, half, wmma::row_major> af[FM];
            wmma::fragment<wmma::matrix_b, 16, 16, 16, half, wmma::col_major> bf[FN];
            #pragma unroll
            for (int i = 0; i < FM; i++)
                wmma::load_matrix_sync(af[i], Ab + (wm * WM + 16 * i) * LD + kk, LD);
            #pragma unroll
            for (int j = 0; j < FN; j++)
                wmma::load_matrix_sync(bf[j], Bb + (wn * WN + 16 * j) * LD + kk, LD);
            #pragma unroll
            for (int i = 0; i < FM; i++)
                #pragma unroll
                for (int j = 0; j < FN; j++)
                    wmma::mma_sync(acc[i][j], af[i], bf[j], acc[i][j]);
        }
        __syncthreads();
    }

    #pragma unroll
    for (int i = 0; i < FM; i++)
        #pragma unroll
        for (int j = 0; j < FN; j++)
            wmma::store_matrix_sync(C + (size_t)(row0 + wm * WM + 16 * i) * N
                                      + (col0 + wn * WN + 16 * j),
                                    acc[i][j], N, wmma::mem_row_major);
}

// in_proj:  BM=128,BN=64,BK=32, warps 2x2 of 64x32, 128 thr, grid (132,2)=264 CTAs (~1.8/SM)
// out_proj: BM=64, BN=32,BK=64, warps 2x2 of 32x16, 128 thr, grid (64,4)=256 CTAs (~1.7/SM)
#define IN_SMEM  ((2*128*(32+8) + 2*64*(32+8)) * 2)    // 30720 B
#define OUT_SMEM ((2*64*(64+8) + 2*32*(64+8)) * 2)     // 27648 B

// ---------------- exact fp32 dt path ----------------
__global__ void dt_kernel(const float* __restrict__ hid, const float* __restrict__ Wp,
                          const float* __restrict__ dt_bias, const float* __restrict__ A_log)
{
    int w = (blockIdx.x * blockDim.x + threadIdx.x) >> 5;
    int lane = threadIdx.x & 31;
    if (w >= BATCH * NHEADS) return;
    int b = w >> 6, h = w & 63;
    const float* hr = hid + (size_t)b * D_MODEL;
    const float* wr = Wp + (size_t)(D_SSM + CONV_DIM + h) * D_MODEL;
    float s = 0.0f;
    #pragma unroll 4
    for (int k = lane; k < D_MODEL; k += 32) s = fmaf(hr[k], wr[k], s);
    #pragma unroll
    for (int o = 16; o; o >>= 1) s += __shfl_xor_sync(0xffffffffu, s, o);
    if (lane == 0) {
        float v = s + dt_bias[h];
        float dt = (v > 20.0f) ? v : log1pf(expf(v));
        g_dt[w] = dt;
        g_dA[w] = expf(-dt * expf(A_log[h]));
    }
}

// ---------------- conv ----------------
__global__ void conv_kernel(const float* __restrict__ conv_state,
                            const float* __restrict__ conv_w,
                            const float* __restrict__ conv_b,
                            float* __restrict__ out_conv)
{
    int i = blockIdx.x * blockDim.x + threadIdx.x;
    if (i >= BATCH * CONV_DIM) return;
    int b = i / CONV_DIM;
    int c = i - b * CONV_DIM;

    float4 s = reinterpret_cast<const float4*>(conv_state)[i];
    float xin = g_zxbcdt[(size_t)b * D_IN_PROJ + D_SSM + c];
    float4 ns = make_float4(s.y, s.z, s.w, xin);
    reinterpret_cast<float4*>(out_conv)[i] = ns;

    float4 w = reinterpret_cast<const float4*>(conv_w)[c];
    float v = ns.x*w.x + ns.y*w.y + ns.z*w.z + ns.w*w.w + conv_b[c];
    v = v / (1.0f + expf(-v));

    if (c < D_SSM) {
        g_x[b * D_SSM + c] = v;
    } else if (c < D_SSM + D_STATE) {
        g_B[b * D_STATE + (c - D_SSM)] = v;
    } else {
        g_C[b * D_STATE + (c - D_SSM - D_STATE)] = v;
    }
}

// ---------------- ssm state update + y + gating (writes yg as fp16) ----------------
__global__ void __launch_bounds__(256)
ssm_kernel(const float* __restrict__ ssm_in,
           const float* __restrict__ Dv,
           float* __restrict__ out_ssm)
{
    int bi = blockIdx.x;              // b*64 + h
    int b = bi >> 6, h = bi & 63;
    int warp = threadIdx.x >> 5, lane = threadIdx.x & 31;

    float dA = g_dA[bi];
    float dt = g_dt[bi];
    float Dh = Dv[h];
    float4 Bv = reinterpret_cast<const float4*>(g_B + b * D_STATE)[lane];
    float4 Cv = reinterpret_cast<const float4*>(g_C + b * D_STATE)[lane];
    const float* xrow = g_x + (size_t)b * D_SSM + h * HEADDIM;
    size_t base = (size_t)bi * (HEADDIM * D_STATE);
    const float4* src = reinterpret_cast<const float4*>(ssm_in + base);
    float4* dst = reinterpret_cast<float4*>(out_ssm + base);

    #pragma unroll
    for (int half_i = 0; half_i < 2; half_i++) {
        float4 s[4];
        float xp[4];
        #pragma unroll
        for (int r = 0; r < 4; r++) {
            int p = warp * 8 + half_i * 4 + r;
            s[r] = __ldcs(&src[p * 32 + lane]);
            xp[r] = __ldg(&xrow[p]);
        }

        float part[4];
        #pragma unroll
        for (int r = 0; r < 4; r++) {
            int p = warp * 8 + half_i * 4 + r;
            float coef = dt * xp[r];
            float4 ns;
            ns.x = fmaf(s[r].x, dA, coef * Bv.x);
            ns.y = fmaf(s[r].y, dA, coef * Bv.y);
            ns.z = fmaf(s[r].z, dA, coef * Bv.z);
            ns.w = fmaf(s[r].w, dA, coef * Bv.w);
            __stcs(&dst[p * 32 + lane], ns);
            part[r] = ns.x*Cv.x + ns.y*Cv.y + ns.z*Cv.z + ns.w*Cv.w;
        }

        #pragma unroll
        for (int r = 0; r < 4; r++) {
            #pragma unroll
            for (int o = 16; o; o >>= 1) part[r] += __shfl_xor_sync(0xffffffffu, part[r], o);
            if (lane == 0) {
                int p = warp * 8 + half_i * 4 + r;
                float y = part[r] + Dh * xp[r];
                float z = g_zxbcdt[(size_t)b * D_IN_PROJ + h * HEADDIM + p];
                g_yg_h[b * D_SSM + h * HEADDIM + p] = __float2half(y * (z / (1.0f + expf(-z))));
            }
        }
    }
}

// ---------------- launch ----------------
extern "C" void kernel_launch(void* const* d_in, const int* in_sizes, int n_in,
                              void* d_out, int out_size)
{
    const float* hid        = (const float*)d_in[0];
    const float* conv_state = (const float*)d_in[1];
    const float* ssm_state  = (const float*)d_in[2];
    const float* in_proj_w  = (const float*)d_in[3];
    const float* conv_w     = (const float*)d_in[4];
    const float* conv_b     = (const float*)d_in[5];
    const float* dt_bias    = (const float*)d_in[6];
    const float* A_log      = (const float*)d_in[7];
    const float* Dv         = (const float*)d_in[8];
    const float* out_proj_w = (const float*)d_in[9];
    float* out = (float*)d_out;

    void* zx_p;  cudaGetSymbolAddress(&zx_p, g_zxbcdt);
    void* yg_p;  cudaGetSymbolAddress(&yg_p, g_yg_h);
    void* hid_p; cudaGetSymbolAddress(&hid_p, g_hid_h);
    void* inw_p; cudaGetSymbolAddress(&inw_p, g_inw_h);
    void* outw_p; cudaGetSymbolAddress(&outw_p, g_outw_h);

    cudaFuncSetAttribute(gemm_f16<128,64,32,64,32>,
                         cudaFuncAttributeMaxDynamicSharedMemorySize, IN_SMEM);
    cudaFuncSetAttribute(gemm_f16<64,32,64,32,16>,
                         cudaFuncAttributeMaxDynamicSharedMemorySize, OUT_SMEM);

    // exact dt/dA path
    dt_kernel<<<(BATCH * NHEADS * 32) / 256, 256>>>(hid, in_proj_w, dt_bias, A_log);

    // fp32 -> fp16 conversions (16 elems/thread)
    f2h_kernel<<<(BATCH * D_MODEL / 16 + 255) / 256, 256>>>(hid, (__half*)hid_p,
                                                            BATCH * D_MODEL / 16);
    f2h_kernel<<<((int)((size_t)N_GEMM * D_MODEL / 16) + 255) / 256, 256>>>(
        in_proj_w, (__half*)inw_p, (int)((size_t)N_GEMM * D_MODEL / 16));
    f2h_kernel<<<((int)((size_t)D_MODEL * D_SSM / 16) + 255) / 256, 256>>>(
        out_proj_w, (__half*)outw_p, (int)((size_t)D_MODEL * D_SSM / 16));

    // in_proj: [256, 8448] = hid @ in_proj_w^T (fp16 in / fp32 acc), 264 CTAs
    gemm_f16<128,64,32,64,32><<<dim3(N_GEMM/64, BATCH/128), 128, IN_SMEM>>>(
        (const __half*)hid_p, (const __half*)inw_p, (float*)zx_p,
        BATCH, D_IN_PROJ, D_MODEL);

    // conv roll + depthwise conv + silu -> new conv_state + x/B/C
    conv_kernel<<<(BATCH * CONV_DIM) / 256, 256>>>(conv_state, conv_w, conv_b, out + OUT_CONV);

    // ssm update (1.07 GB pass) + fused y/gating -> yg fp16
    ssm_kernel<<<BATCH * NHEADS, 256>>>(ssm_state, Dv, out + OUT_SSM);

    // out_proj: [256, 2048] = yg @ out_proj_w^T, 256 CTAs
    gemm_f16<64,32,64,32,16><<<dim3(D_MODEL/32, BATCH/64), 128, OUT_SMEM>>>(
        (const __half*)yg_p, (const __half*)outw_p, out, BATCH, D_MODEL, D_SSM);
}